// round 4
// baseline (speedup 1.0000x reference)
#include <cuda_runtime.h>
#include <math.h>
#include <stdint.h>

#define BATCH 4
#define N1V 2048
#define N2V 2048
#define DIMV 512
#define NHEAD 8
#define HD 64

// Scratch (device globals: no allocation allowed in kernel_launch)
__device__ __align__(256) float g_Q   [BATCH * N1V * DIMV];
__device__ __align__(256) float g_K   [BATCH * N2V * DIMV];
__device__ __align__(256) float g_V   [BATCH * N2V * DIMV];
__device__ __align__(256) float g_W2  [BATCH * N1V * DIMV];
__device__ __align__(256) float g_CTX [BATCH * N1V * DIMV];
__device__ __align__(256) float g_CTXO[BATCH * N1V * DIMV];
// tf32-pre-rounded operands
__device__ __align__(256) float g_g1r [BATCH * N1V * DIMV];
__device__ __align__(256) float g_g2r [BATCH * N2V * DIMV];
__device__ __align__(256) float g_Wqr [DIMV * DIMV];
__device__ __align__(256) float g_Wkr [DIMV * DIMV];
__device__ __align__(256) float g_Wvr [DIMV * DIMV];
__device__ __align__(256) float g_Wor [DIMV * DIMV];
__device__ __align__(256) float g_Wr  [DIMV * DIMV];

// ---------------------------------------------------------------------------
__device__ __forceinline__ uint32_t f2tf(float x) {
    uint32_t u;
    asm("cvt.rna.tf32.f32 %0, %1;" : "=r"(u) : "f"(x));
    return u;
}

__device__ __forceinline__ void mma_tf32(float* c, const uint32_t* a, const uint32_t* b) {
    asm volatile(
        "mma.sync.aligned.m16n8k8.row.col.f32.tf32.tf32.f32 "
        "{%0,%1,%2,%3}, {%4,%5,%6,%7}, {%8,%9}, {%0,%1,%2,%3};\n"
        : "+f"(c[0]), "+f"(c[1]), "+f"(c[2]), "+f"(c[3])
        : "r"(a[0]), "r"(a[1]), "r"(a[2]), "r"(a[3]), "r"(b[0]), "r"(b[1]));
}

__device__ __forceinline__ void cp16(uint32_t dst_smem, const void* src) {
    asm volatile("cp.async.cg.shared.global [%0], [%1], 16;\n" :: "r"(dst_smem), "l"(src));
}
#define CP_COMMIT() asm volatile("cp.async.commit_group;\n" ::: "memory")
#define CP_WAIT(n)  asm volatile("cp.async.wait_group %0;\n" :: "n"(n) : "memory")

__device__ __forceinline__ uint32_t smaddr(const void* p) {
    return (uint32_t)__cvta_generic_to_shared(p);
}

// ---------------------------------------------------------------------------
// Elementwise tf32 pre-round: out[i] = round_rna_tf32(in[i]) (as f32 bits)
// ---------------------------------------------------------------------------
__global__ __launch_bounds__(256) void round_tf32_k(
    const float* __restrict__ in, float* __restrict__ out, int n4)
{
    const int i = blockIdx.x * 256 + threadIdx.x;
    if (i < n4) {
        float4 v = ((const float4*)in)[i];
        float4 r;
        r.x = __uint_as_float(f2tf(v.x));
        r.y = __uint_as_float(f2tf(v.y));
        r.z = __uint_as_float(f2tf(v.z));
        r.w = __uint_as_float(f2tf(v.w));
        ((float4*)out)[i] = r;
    }
}

// ---------------------------------------------------------------------------
// tf32 tensor-core GEMM: C[M][N] = A[M][K] @ B (+bias).  K=512 fixed.
// A and Wt must be tf32-pre-rounded. 3-stage cp.async pipeline.
// 128x128 block, BK=32, 256 threads (8 warps 2x4), warp tile 64x32.
// ---------------------------------------------------------------------------
#define AS_STRIDE 36
#define BS_STRIDE_NT 132
#define STG_U32 4608                       // per-stage u32 (fits 128*36 and 32*132)
#define GEMM_SMEM (6 * STG_U32 * 4)        // 110592 B

template<bool TRANSB>
__device__ __forceinline__ void g_prefetch(
    uint32_t* As, uint32_t* Bs, const float* A, const float* Wt,
    int m0, int n0, int k0, int K, int N, int t)
{
#pragma unroll
    for (int j = 0; j < 4; j++) {
        const int idx = t + 256 * j;
        const int row = idx >> 3, c4 = (idx & 7) << 2;
        cp16(smaddr(&As[row * AS_STRIDE + c4]),
             A + (size_t)(m0 + row) * K + k0 + c4);
    }
    if (TRANSB) {
#pragma unroll
        for (int j = 0; j < 4; j++) {
            const int idx = t + 256 * j;
            const int row = idx >> 3, c4 = (idx & 7) << 2;
            cp16(smaddr(&Bs[row * AS_STRIDE + c4]),
                 Wt + (size_t)(n0 + row) * K + k0 + c4);
        }
    } else {
#pragma unroll
        for (int j = 0; j < 4; j++) {
            const int idx = t + 256 * j;
            const int row = idx >> 5, n4 = (idx & 31) << 2;
            cp16(smaddr(&Bs[row * BS_STRIDE_NT + n4]),
                 Wt + (size_t)(k0 + row) * N + n0 + n4);
        }
    }
}

template<bool TRANSB, bool HASBIAS, bool ROUND>
__global__ __launch_bounds__(256, 2) void gemm_tc(
    const float* __restrict__ A, const float* __restrict__ Wt,
    const float* __restrict__ bias, float* __restrict__ C,
    int M, int N, int K)
{
    extern __shared__ uint32_t sm[];

    const int t    = threadIdx.x;
    const int w    = t >> 5;
    const int lane = t & 31;
    const int g    = lane >> 2;
    const int tid4 = lane & 3;
    const int m0   = blockIdx.y * 128, n0 = blockIdx.x * 128;
    const int warpM = (w >> 2) * 64;
    const int warpN = (w & 3) * 32;

    float acc[4][4][4];
#pragma unroll
    for (int mi = 0; mi < 4; mi++)
#pragma unroll
        for (int ni = 0; ni < 4; ni++)
#pragma unroll
            for (int c = 0; c < 4; c++) acc[mi][ni][c] = 0.f;

    const int nIter = K / 32;   // 16

    g_prefetch<TRANSB>(sm, sm + 3 * STG_U32, A, Wt, m0, n0, 0, K, N, t);
    CP_COMMIT();
    g_prefetch<TRANSB>(sm + STG_U32, sm + 4 * STG_U32, A, Wt, m0, n0, 32, K, N, t);
    CP_COMMIT();

    int st = 0;
    for (int it = 0; it < nIter; it++) {
        if (it < nIter - 1) CP_WAIT(1); else CP_WAIT(0);
        __syncthreads();
        if (it + 2 < nIter) {
            const int s2 = (st + 2) % 3;
            g_prefetch<TRANSB>(sm + s2 * STG_U32, sm + (3 + s2) * STG_U32,
                               A, Wt, m0, n0, (it + 2) * 32, K, N, t);
            CP_COMMIT();
        }
        uint32_t* As = sm + st * STG_U32;
        uint32_t* Bs = sm + (3 + st) * STG_U32;

#pragma unroll
        for (int ks = 0; ks < 4; ks++) {
            uint32_t a[4][4], b[4][2];
            const int kc = tid4 + 8 * ks;
#pragma unroll
            for (int mi = 0; mi < 4; mi++) {
                const int r = warpM + 16 * mi + g;
                a[mi][0] = As[r * AS_STRIDE + kc];
                a[mi][1] = As[(r + 8) * AS_STRIDE + kc];
                a[mi][2] = As[r * AS_STRIDE + kc + 4];
                a[mi][3] = As[(r + 8) * AS_STRIDE + kc + 4];
            }
#pragma unroll
            for (int ni = 0; ni < 4; ni++) {
                const int n = warpN + 8 * ni + g;
                if (TRANSB) {
                    b[ni][0] = Bs[n * AS_STRIDE + kc];
                    b[ni][1] = Bs[n * AS_STRIDE + kc + 4];
                } else {
                    b[ni][0] = Bs[kc * BS_STRIDE_NT + n];
                    b[ni][1] = Bs[(kc + 4) * BS_STRIDE_NT + n];
                }
            }
#pragma unroll
            for (int mi = 0; mi < 4; mi++)
#pragma unroll
                for (int ni = 0; ni < 4; ni++)
                    mma_tf32(acc[mi][ni], a[mi], b[ni]);
        }
        st = (st + 1) % 3;
    }

#pragma unroll
    for (int mi = 0; mi < 4; mi++) {
#pragma unroll
        for (int ni = 0; ni < 4; ni++) {
            const int row = m0 + warpM + 16 * mi + g;
            const int col = n0 + warpN + 8 * ni + 2 * tid4;
            float bx = 0.f, by = 0.f;
            if (HASBIAS) { bx = bias[col]; by = bias[col + 1]; }
            float v00 = acc[mi][ni][0] + bx, v01 = acc[mi][ni][1] + by;
            float v10 = acc[mi][ni][2] + bx, v11 = acc[mi][ni][3] + by;
            if (ROUND) {
                v00 = __uint_as_float(f2tf(v00)); v01 = __uint_as_float(f2tf(v01));
                v10 = __uint_as_float(f2tf(v10)); v11 = __uint_as_float(f2tf(v11));
            }
            *(float2*)(C + (size_t)row * N + col)       = make_float2(v00, v01);
            *(float2*)(C + (size_t)(row + 8) * N + col) = make_float2(v10, v11);
        }
    }
}

// ---------------------------------------------------------------------------
// Flash attention, tf32 TC. Q/K/V must be tf32-pre-rounded.
// Block = 128 q-rows x (b,h). 256 threads, 8 warps x 16 q-rows. BKV=64.
// Q fragments in registers; Ps aliases Qs; K/V double-buffered cp.async.
// ---------------------------------------------------------------------------
#define BQ 128
#define BKV 64
#define ASTR 68
#define KV_BASE   (BQ * ASTR)                // after Qs/Ps region
#define V_BASE    (KV_BASE + 2 * BKV * ASTR)
#define ATTN_SMEM ((BQ * ASTR + 4 * BKV * ASTR) * 4)   // 104448 B

__device__ __forceinline__ void kv_prefetch(
    uint32_t* sm, const float* Kb, const float* Vb, int kt, int st, int t)
{
    uint32_t* Ks = sm + KV_BASE + st * BKV * ASTR;
    uint32_t* Vs = sm + V_BASE  + st * BKV * ASTR;
#pragma unroll
    for (int j = 0; j < 4; j++) {
        const int idx = t + 256 * j;
        const int row = idx >> 4, c4 = (idx & 15) << 2;
        cp16(smaddr(&Ks[row * ASTR + c4]),
             Kb + (size_t)(kt * BKV + row) * DIMV + c4);
    }
#pragma unroll
    for (int j = 0; j < 4; j++) {
        const int idx = t + 256 * j;
        const int row = idx >> 4, c4 = (idx & 15) << 2;
        cp16(smaddr(&Vs[row * ASTR + c4]),
             Vb + (size_t)(kt * BKV + row) * DIMV + c4);
    }
}

__global__ __launch_bounds__(256) void attn_tc(
    const float* __restrict__ Q, const float* __restrict__ K,
    const float* __restrict__ V, float* __restrict__ ctx)
{
    extern __shared__ uint32_t sm[];
    uint32_t* Qs = sm;     // aliased as Ps after fragment extraction
    uint32_t* Ps = sm;

    const int qb = blockIdx.x;
    const int bh = blockIdx.y;
    const int b  = bh >> 3, h = bh & 7;
    const int t  = threadIdx.x;
    const int w  = t >> 5, lane = t & 31;
    const int g  = lane >> 2, tid4 = lane & 3;

    const float* Qb = Q + ((size_t)b * N1V + qb * BQ) * DIMV + h * HD;
    const float* Kb = K + (size_t)b * N2V * DIMV + h * HD;
    const float* Vb = V + (size_t)b * N2V * DIMV + h * HD;

    // Q tile via cp.async (group 0)
#pragma unroll
    for (int j = 0; j < 8; j++) {
        const int idx = t + 256 * j;
        const int row = idx >> 4, c4 = (idx & 15) << 2;
        cp16(smaddr(&Qs[row * ASTR + c4]), Qb + (size_t)row * DIMV + c4);
    }
    CP_COMMIT();
    // KV tile 0 (group 1)
    kv_prefetch(sm, Kb, Vb, 0, 0, t);
    CP_COMMIT();

    CP_WAIT(1);          // Q done (KV0 may be in flight)
    __syncthreads();

    // Extract Q fragments (warp-private rows w*16..w*16+15)
    uint32_t qf[8][4];
    const int r = w * 16 + g;
#pragma unroll
    for (int ks = 0; ks < 8; ks++) {
        const int kc = tid4 + 8 * ks;
        qf[ks][0] = Qs[r * ASTR + kc];
        qf[ks][1] = Qs[(r + 8) * ASTR + kc];
        qf[ks][2] = Qs[r * ASTR + kc + 4];
        qf[ks][3] = Qs[(r + 8) * ASTR + kc + 4];
    }

    float m0v = -1e30f, m1v = -1e30f, l0 = 0.f, l1 = 0.f;
    float o[8][4];
#pragma unroll
    for (int ni = 0; ni < 8; ni++)
#pragma unroll
        for (int c = 0; c < 4; c++) o[ni][c] = 0.f;

    int st = 0;
    for (int kt = 0; kt < N2V / BKV; kt++) {
        CP_WAIT(0);
        __syncthreads();
        if (kt + 1 < N2V / BKV) {
            kv_prefetch(sm, Kb, Vb, kt + 1, st ^ 1, t);
            CP_COMMIT();
        }
        uint32_t* Ks = sm + KV_BASE + st * BKV * ASTR;
        uint32_t* Vs = sm + V_BASE  + st * BKV * ASTR;

        // S = Q @ K^T (16 x 64 per warp)
        float s[8][4];
#pragma unroll
        for (int ni = 0; ni < 8; ni++)
#pragma unroll
            for (int c = 0; c < 4; c++) s[ni][c] = 0.f;

#pragma unroll
        for (int ks = 0; ks < 8; ks++) {
            const int kc = tid4 + 8 * ks;
#pragma unroll
            for (int ni = 0; ni < 8; ni++) {
                uint32_t bf[2];
                const int n = 8 * ni + g;
                bf[0] = Ks[n * ASTR + kc];
                bf[1] = Ks[n * ASTR + kc + 4];
                mma_tf32(s[ni], qf[ks], bf);
            }
        }

        // online softmax
        float mx0 = -1e30f, mx1 = -1e30f;
#pragma unroll
        for (int ni = 0; ni < 8; ni++) {
#pragma unroll
            for (int c = 0; c < 4; c++) s[ni][c] *= 0.125f;   // 1/sqrt(64)
            mx0 = fmaxf(mx0, fmaxf(s[ni][0], s[ni][1]));
            mx1 = fmaxf(mx1, fmaxf(s[ni][2], s[ni][3]));
        }
        mx0 = fmaxf(mx0, __shfl_xor_sync(0xffffffffu, mx0, 1));
        mx0 = fmaxf(mx0, __shfl_xor_sync(0xffffffffu, mx0, 2));
        mx1 = fmaxf(mx1, __shfl_xor_sync(0xffffffffu, mx1, 1));
        mx1 = fmaxf(mx1, __shfl_xor_sync(0xffffffffu, mx1, 2));
        const float mn0 = fmaxf(m0v, mx0);
        const float mn1 = fmaxf(m1v, mx1);
        float sum0 = 0.f, sum1 = 0.f;
#pragma unroll
        for (int ni = 0; ni < 8; ni++) {
            s[ni][0] = __expf(s[ni][0] - mn0);
            s[ni][1] = __expf(s[ni][1] - mn0);
            s[ni][2] = __expf(s[ni][2] - mn1);
            s[ni][3] = __expf(s[ni][3] - mn1);
            sum0 += s[ni][0] + s[ni][1];
            sum1 += s[ni][2] + s[ni][3];
        }
        sum0 += __shfl_xor_sync(0xffffffffu, sum0, 1);
        sum0 += __shfl_xor_sync(0xffffffffu, sum0, 2);
        sum1 += __shfl_xor_sync(0xffffffffu, sum1, 1);
        sum1 += __shfl_xor_sync(0xffffffffu, sum1, 2);
        const float al0 = __expf(m0v - mn0);
        const float al1 = __expf(m1v - mn1);
        m0v = mn0; m1v = mn1;
        l0 = l0 * al0 + sum0;
        l1 = l1 * al1 + sum1;
#pragma unroll
        for (int ni = 0; ni < 8; ni++) {
            o[ni][0] *= al0; o[ni][1] *= al0;
            o[ni][2] *= al1; o[ni][3] *= al1;
            const int col = 2 * tid4 + 8 * ni;
            Ps[r * ASTR + col]           = f2tf(s[ni][0]);
            Ps[r * ASTR + col + 1]       = f2tf(s[ni][1]);
            Ps[(r + 8) * ASTR + col]     = f2tf(s[ni][2]);
            Ps[(r + 8) * ASTR + col + 1] = f2tf(s[ni][3]);
        }
        __syncwarp();

        // O += P @ V
#pragma unroll
        for (int ks = 0; ks < 8; ks++) {
            const int kc = tid4 + 8 * ks;
            uint32_t a[4];
            a[0] = Ps[r * ASTR + kc];
            a[1] = Ps[(r + 8) * ASTR + kc];
            a[2] = Ps[r * ASTR + kc + 4];
            a[3] = Ps[(r + 8) * ASTR + kc + 4];
#pragma unroll
            for (int ni = 0; ni < 8; ni++) {
                uint32_t bf[2];
                const int n = 8 * ni + g;
                bf[0] = Vs[kc * ASTR + n];
                bf[1] = Vs[(kc + 4) * ASTR + n];
                mma_tf32(o[ni], a, bf);
            }
        }
        __syncwarp();
        st ^= 1;
    }

    // write context, tf32-rounded (feeds Wo GEMM via cp.async)
    const float inv0 = 1.0f / l0;
    const float inv1 = 1.0f / l1;
    const int orow = qb * BQ + w * 16 + g;
#pragma unroll
    for (int ni = 0; ni < 8; ni++) {
        const int col = h * HD + 2 * tid4 + 8 * ni;
        float2 v0 = make_float2(__uint_as_float(f2tf(o[ni][0] * inv0)),
                                __uint_as_float(f2tf(o[ni][1] * inv0)));
        float2 v1 = make_float2(__uint_as_float(f2tf(o[ni][2] * inv1)),
                                __uint_as_float(f2tf(o[ni][3] * inv1)));
        *(float2*)(ctx + ((size_t)b * N1V + orow) * DIMV + col)     = v0;
        *(float2*)(ctx + ((size_t)b * N1V + orow + 8) * DIMV + col) = v1;
    }
}

// ---------------------------------------------------------------------------
__global__ __launch_bounds__(128) void score_kernel(
    const float* __restrict__ A, const float* __restrict__ Bc,
    const float* __restrict__ scale, float* __restrict__ out)
{
    const int row = blockIdx.x;
    const int t = threadIdx.x;
    const float4 x = ((const float4*)(A + (size_t)row * DIMV))[t];
    const float4 y = ((const float4*)(Bc + (size_t)row * DIMV))[t];
    float s = x.x * y.x + x.y * y.y + x.z * y.z + x.w * y.w;
#pragma unroll
    for (int off = 16; off; off >>= 1)
        s += __shfl_xor_sync(0xffffffffu, s, off);
    __shared__ float red[4];
    if ((t & 31) == 0) red[t >> 5] = s;
    __syncthreads();
    if (t == 0) {
        const float tot = red[0] + red[1] + red[2] + red[3];
        const float z = tot * scale[0];
        out[row] = fmaxf(z, 0.f) + log1pf(__expf(-fabsf(z)));
    }
}

// ---------------------------------------------------------------------------
extern "C" void kernel_launch(void* const* d_in, const int* in_sizes, int n_in,
                              void* d_out, int out_size)
{
    const float* g1    = (const float*)d_in[0];
    const float* g2    = (const float*)d_in[1];
    const float* Wq    = (const float*)d_in[2];
    const float* bq    = (const float*)d_in[3];
    const float* Wk    = (const float*)d_in[4];
    const float* bk    = (const float*)d_in[5];
    const float* Wv    = (const float*)d_in[6];
    const float* bv    = (const float*)d_in[7];
    const float* Wo    = (const float*)d_in[8];
    const float* bo    = (const float*)d_in[9];
    const float* Wb    = (const float*)d_in[10];
    const float* scale = (const float*)d_in[11];
    float* out = (float*)d_out;

    float *Qp, *Kp, *Vp, *W2p, *CTXp, *CTXOp;
    float *g1r, *g2r, *Wqr, *Wkr, *Wvr, *Wor, *Wr;
    cudaGetSymbolAddress((void**)&Qp,    g_Q);
    cudaGetSymbolAddress((void**)&Kp,    g_K);
    cudaGetSymbolAddress((void**)&Vp,    g_V);
    cudaGetSymbolAddress((void**)&W2p,   g_W2);
    cudaGetSymbolAddress((void**)&CTXp,  g_CTX);
    cudaGetSymbolAddress((void**)&CTXOp, g_CTXO);
    cudaGetSymbolAddress((void**)&g1r,   g_g1r);
    cudaGetSymbolAddress((void**)&g2r,   g_g2r);
    cudaGetSymbolAddress((void**)&Wqr,   g_Wqr);
    cudaGetSymbolAddress((void**)&Wkr,   g_Wkr);
    cudaGetSymbolAddress((void**)&Wvr,   g_Wvr);
    cudaGetSymbolAddress((void**)&Wor,   g_Wor);
    cudaGetSymbolAddress((void**)&Wr,    g_Wr);

    cudaFuncSetAttribute((const void*)gemm_tc<true,  true,  true >, cudaFuncAttributeMaxDynamicSharedMemorySize, GEMM_SMEM);
    cudaFuncSetAttribute((const void*)gemm_tc<false, false, false>, cudaFuncAttributeMaxDynamicSharedMemorySize, GEMM_SMEM);
    cudaFuncSetAttribute((const void*)gemm_tc<true,  true,  false>, cudaFuncAttributeMaxDynamicSharedMemorySize, GEMM_SMEM);
    cudaFuncSetAttribute((const void*)attn_tc, cudaFuncAttributeMaxDynamicSharedMemorySize, ATTN_SMEM);

    const int M = BATCH * N1V;                 // 8192
    const int NBIG4 = (M * DIMV) / 4;          // 1048576
    const int NW4   = (DIMV * DIMV) / 4;       // 65536

    round_tf32_k<<<(NBIG4 + 255) / 256, 256>>>(g1, g1r, NBIG4);
    round_tf32_k<<<(NBIG4 + 255) / 256, 256>>>(g2, g2r, NBIG4);
    round_tf32_k<<<(NW4 + 255) / 256, 256>>>(Wq, Wqr, NW4);
    round_tf32_k<<<(NW4 + 255) / 256, 256>>>(Wk, Wkr, NW4);
    round_tf32_k<<<(NW4 + 255) / 256, 256>>>(Wv, Wvr, NW4);
    round_tf32_k<<<(NW4 + 255) / 256, 256>>>(Wo, Wor, NW4);
    round_tf32_k<<<(NW4 + 255) / 256, 256>>>(Wb, Wr,  NW4);

    dim3 gg(DIMV / 128, M / 128);              // (4, 64)

    gemm_tc<true,  true,  true ><<<gg, 256, GEMM_SMEM>>>(g1r,  Wqr, bq,      Qp,    M, DIMV, DIMV);
    gemm_tc<true,  true,  true ><<<gg, 256, GEMM_SMEM>>>(g2r,  Wkr, bk,      Kp,    M, DIMV, DIMV);
    gemm_tc<true,  true,  true ><<<gg, 256, GEMM_SMEM>>>(g2r,  Wvr, bv,      Vp,    M, DIMV, DIMV);
    gemm_tc<false, false, false><<<gg, 256, GEMM_SMEM>>>(g1r,  Wr,  nullptr, W2p,   M, DIMV, DIMV);

    attn_tc<<<dim3(N1V / BQ, BATCH * NHEAD), 256, ATTN_SMEM>>>(Qp, Kp, Vp, CTXp);

    gemm_tc<true,  true,  false><<<gg, 256, GEMM_SMEM>>>(CTXp, Wor, bo,      CTXOp, M, DIMV, DIMV);

    score_kernel<<<M, 128>>>(W2p, CTXOp, scale, out);
}

// round 6
// speedup vs baseline: 1.1213x; 1.1213x over previous
#include <cuda_runtime.h>
#include <math.h>
#include <stdint.h>

#define BATCH 4
#define N1V 2048
#define N2V 2048
#define DIMV 512
#define NHEAD 8
#define HD 64

// Scratch (device globals: no allocation allowed in kernel_launch)
__device__ __align__(256) float g_Q   [BATCH * N1V * DIMV];
__device__ __align__(256) float g_K   [BATCH * N2V * DIMV];
__device__ __align__(256) float g_V   [BATCH * N2V * DIMV];
__device__ __align__(256) float g_CTX [BATCH * N1V * DIMV];
__device__ __align__(256) float g_U   [BATCH * N1V * DIMV];
__device__ __align__(256) float g_g1r [BATCH * N1V * DIMV];
__device__ __align__(256) float g_g2r [BATCH * N2V * DIMV];
__device__ __align__(256) float g_Wqr [DIMV * DIMV];
__device__ __align__(256) float g_Wkr [DIMV * DIMV];
__device__ __align__(256) float g_Wvr [DIMV * DIMV];
__device__ __align__(256) float g_Wor [DIMV * DIMV];
__device__ __align__(256) float g_Wr  [DIMV * DIMV];
__device__ __align__(256) float g_M   [DIMV * DIMV];     // W @ Wo (tf32-rounded)
__device__ __align__(256) float g_wbo [DIMV];            // W @ bo

// ---------------------------------------------------------------------------
__device__ __forceinline__ uint32_t f2tf(float x) {
    uint32_t u;
    asm("cvt.rna.tf32.f32 %0, %1;" : "=r"(u) : "f"(x));
    return u;
}

__device__ __forceinline__ void mma_tf32(float* c, const uint32_t* a, const uint32_t* b) {
    asm volatile(
        "mma.sync.aligned.m16n8k8.row.col.f32.tf32.tf32.f32 "
        "{%0,%1,%2,%3}, {%4,%5,%6,%7}, {%8,%9}, {%0,%1,%2,%3};\n"
        : "+f"(c[0]), "+f"(c[1]), "+f"(c[2]), "+f"(c[3])
        : "r"(a[0]), "r"(a[1]), "r"(a[2]), "r"(a[3]), "r"(b[0]), "r"(b[1]));
}

__device__ __forceinline__ void cp16(uint32_t dst_smem, const void* src) {
    asm volatile("cp.async.cg.shared.global [%0], [%1], 16;\n" :: "r"(dst_smem), "l"(src));
}
#define CP_COMMIT() asm volatile("cp.async.commit_group;\n" ::: "memory")
#define CP_WAIT(n)  asm volatile("cp.async.wait_group %0;\n" :: "n"(n) : "memory")

__device__ __forceinline__ uint32_t smaddr(const void* p) {
    return (uint32_t)__cvta_generic_to_shared(p);
}

// ---------------------------------------------------------------------------
// Elementwise tf32 pre-round
// ---------------------------------------------------------------------------
__global__ __launch_bounds__(256) void round_tf32_k(
    const float* __restrict__ in, float* __restrict__ out, int n4)
{
    const int i = blockIdx.x * 256 + threadIdx.x;
    if (i < n4) {
        float4 v = ((const float4*)in)[i];
        float4 r;
        r.x = __uint_as_float(f2tf(v.x));
        r.y = __uint_as_float(f2tf(v.y));
        r.z = __uint_as_float(f2tf(v.z));
        r.w = __uint_as_float(f2tf(v.w));
        ((float4*)out)[i] = r;
    }
}

// ---------------------------------------------------------------------------
// tf32 TC GEMM, 2-stage cp.async pipeline. Inputs must be tf32-pre-rounded.
// C[M][N] = A[M][K] @ B (+bias). TRANSB: B[k][n] = Wt[n][k]. else Wt[k][n].
// 128x128 block, BK=32, 256 threads (8 warps 2x4), warp tile 64x32.
// Smem: 2 stages x (A 128x36 + B pad) = 73728 B -> 2 blocks/SM.
// ---------------------------------------------------------------------------
#define AS_STRIDE 36
#define BS_STRIDE_NT 132
#define STG_U32 4608
#define GEMM_SMEM (4 * STG_U32 * 4)        // 73728 B

template<bool TRANSB>
__device__ __forceinline__ void g_prefetch(
    uint32_t* As, uint32_t* Bs, const float* A, const float* Wt,
    int m0, int n0, int k0, int K, int N, int t)
{
#pragma unroll
    for (int j = 0; j < 4; j++) {
        const int idx = t + 256 * j;
        const int row = idx >> 3, c4 = (idx & 7) << 2;
        cp16(smaddr(&As[row * AS_STRIDE + c4]),
             A + (size_t)(m0 + row) * K + k0 + c4);
    }
    if (TRANSB) {
#pragma unroll
        for (int j = 0; j < 4; j++) {
            const int idx = t + 256 * j;
            const int row = idx >> 3, c4 = (idx & 7) << 2;
            cp16(smaddr(&Bs[row * AS_STRIDE + c4]),
                 Wt + (size_t)(n0 + row) * K + k0 + c4);
        }
    } else {
#pragma unroll
        for (int j = 0; j < 4; j++) {
            const int idx = t + 256 * j;
            const int row = idx >> 5, n4 = (idx & 31) << 2;
            cp16(smaddr(&Bs[row * BS_STRIDE_NT + n4]),
                 Wt + (size_t)(k0 + row) * N + n0 + n4);
        }
    }
}

template<bool TRANSB, bool HASBIAS, bool ROUND>
__global__ __launch_bounds__(256, 2) void gemm_tc(
    const float* __restrict__ A, const float* __restrict__ Wt,
    const float* __restrict__ bias, float* __restrict__ C,
    int M, int N, int K)
{
    extern __shared__ uint32_t sm[];

    const int t    = threadIdx.x;
    const int w    = t >> 5;
    const int lane = t & 31;
    const int g    = lane >> 2;
    const int tid4 = lane & 3;
    const int m0   = blockIdx.y * 128, n0 = blockIdx.x * 128;
    const int warpM = (w >> 2) * 64;
    const int warpN = (w & 3) * 32;

    float acc[4][4][4];
#pragma unroll
    for (int mi = 0; mi < 4; mi++)
#pragma unroll
        for (int ni = 0; ni < 4; ni++)
#pragma unroll
            for (int c = 0; c < 4; c++) acc[mi][ni][c] = 0.f;

    const int nIter = K / 32;   // 16

    g_prefetch<TRANSB>(sm, sm + 2 * STG_U32, A, Wt, m0, n0, 0, K, N, t);
    CP_COMMIT();

    int st = 0;
    for (int it = 0; it < nIter; it++) {
        if (it + 1 < nIter) {
            g_prefetch<TRANSB>(sm + (st ^ 1) * STG_U32, sm + (2 + (st ^ 1)) * STG_U32,
                               A, Wt, m0, n0, (it + 1) * 32, K, N, t);
            CP_COMMIT();
            CP_WAIT(1);
        } else {
            CP_WAIT(0);
        }
        __syncthreads();

        uint32_t* As = sm + st * STG_U32;
        uint32_t* Bs = sm + (2 + st) * STG_U32;

#pragma unroll
        for (int ks = 0; ks < 4; ks++) {
            uint32_t a[4][4], b[4][2];
            const int kc = tid4 + 8 * ks;
#pragma unroll
            for (int mi = 0; mi < 4; mi++) {
                const int r = warpM + 16 * mi + g;
                a[mi][0] = As[r * AS_STRIDE + kc];
                a[mi][1] = As[(r + 8) * AS_STRIDE + kc];
                a[mi][2] = As[r * AS_STRIDE + kc + 4];
                a[mi][3] = As[(r + 8) * AS_STRIDE + kc + 4];
            }
#pragma unroll
            for (int ni = 0; ni < 4; ni++) {
                const int n = warpN + 8 * ni + g;
                if (TRANSB) {
                    b[ni][0] = Bs[n * AS_STRIDE + kc];
                    b[ni][1] = Bs[n * AS_STRIDE + kc + 4];
                } else {
                    b[ni][0] = Bs[kc * BS_STRIDE_NT + n];
                    b[ni][1] = Bs[(kc + 4) * BS_STRIDE_NT + n];
                }
            }
#pragma unroll
            for (int mi = 0; mi < 4; mi++)
#pragma unroll
                for (int ni = 0; ni < 4; ni++)
                    mma_tf32(acc[mi][ni], a[mi], b[ni]);
        }
        __syncthreads();   // all reads of stage st done before next-iter prefetch
        st ^= 1;
    }

#pragma unroll
    for (int mi = 0; mi < 4; mi++) {
#pragma unroll
        for (int ni = 0; ni < 4; ni++) {
            const int row = m0 + warpM + 16 * mi + g;
            const int col = n0 + warpN + 8 * ni + 2 * tid4;
            float bx = 0.f, by = 0.f;
            if (HASBIAS) { bx = bias[col]; by = bias[col + 1]; }
            float v00 = acc[mi][ni][0] + bx, v01 = acc[mi][ni][1] + by;
            float v10 = acc[mi][ni][2] + bx, v11 = acc[mi][ni][3] + by;
            if (ROUND) {
                v00 = __uint_as_float(f2tf(v00)); v01 = __uint_as_float(f2tf(v01));
                v10 = __uint_as_float(f2tf(v10)); v11 = __uint_as_float(f2tf(v11));
            }
            *(float2*)(C + (size_t)row * N + col)       = make_float2(v00, v01);
            *(float2*)(C + (size_t)(row + 8) * N + col) = make_float2(v10, v11);
        }
    }
}

// ---------------------------------------------------------------------------
// Flash attention, tf32 TC (round-3 proven version; ctx written full fp32).
// Block = 128 q-rows x (b,h). 4 warps x 32 q-rows. BKV=64.
// ---------------------------------------------------------------------------
#define BQ 128
#define BKV 64
#define AT_STRIDE 68
#define ATTN_SMEM ((BQ + BKV + BKV + BQ) * AT_STRIDE * 4)

__global__ __launch_bounds__(128) void attn_tc(
    const float* __restrict__ Q, const float* __restrict__ K,
    const float* __restrict__ V, float* __restrict__ ctx)
{
    extern __shared__ uint32_t smA[];
    uint32_t* Qs = smA;
    uint32_t* Ks = Qs + BQ * AT_STRIDE;
    uint32_t* Vs = Ks + BKV * AT_STRIDE;
    uint32_t* Ps = Vs + BKV * AT_STRIDE;

    const int qb = blockIdx.x;
    const int bh = blockIdx.y;
    const int b  = bh >> 3, h = bh & 7;
    const int t  = threadIdx.x;
    const int w  = t >> 5, lane = t & 31;
    const int g  = lane >> 2, tid4 = lane & 3;

    const float* Qb = Q + ((size_t)b * N1V + qb * BQ) * DIMV + h * HD;
    const float* Kb = K + (size_t)b * N2V * DIMV + h * HD;
    const float* Vb = V + (size_t)b * N2V * DIMV + h * HD;

#pragma unroll
    for (int j = 0; j < 16; j++) {
        const int idx = t + 128 * j;
        const int row = idx >> 4, c4 = (idx & 15) << 2;
        float4 v = *(const float4*)(Qb + (size_t)row * DIMV + c4);
        uint32_t* p = &Qs[row * AT_STRIDE + c4];
        p[0] = f2tf(v.x); p[1] = f2tf(v.y); p[2] = f2tf(v.z); p[3] = f2tf(v.w);
    }

    float m_[2][2], l_[2][2], o[2][8][4];
#pragma unroll
    for (int mi = 0; mi < 2; mi++) {
        m_[mi][0] = -1e30f; m_[mi][1] = -1e30f;
        l_[mi][0] = 0.f;    l_[mi][1] = 0.f;
#pragma unroll
        for (int ni = 0; ni < 8; ni++)
#pragma unroll
            for (int c = 0; c < 4; c++) o[mi][ni][c] = 0.f;
    }

    for (int kt = 0; kt < N2V / BKV; kt++) {
        __syncthreads();
#pragma unroll
        for (int j = 0; j < 8; j++) {
            const int idx = t + 128 * j;
            const int row = idx >> 4, c4 = (idx & 15) << 2;
            float4 kv = *(const float4*)(Kb + (size_t)(kt * BKV + row) * DIMV + c4);
            uint32_t* pk = &Ks[row * AT_STRIDE + c4];
            pk[0] = f2tf(kv.x); pk[1] = f2tf(kv.y); pk[2] = f2tf(kv.z); pk[3] = f2tf(kv.w);
            float4 vv = *(const float4*)(Vb + (size_t)(kt * BKV + row) * DIMV + c4);
            uint32_t* pv = &Vs[row * AT_STRIDE + c4];
            pv[0] = f2tf(vv.x); pv[1] = f2tf(vv.y); pv[2] = f2tf(vv.z); pv[3] = f2tf(vv.w);
        }
        __syncthreads();

        float s[2][8][4];
#pragma unroll
        for (int mi = 0; mi < 2; mi++)
#pragma unroll
            for (int ni = 0; ni < 8; ni++)
#pragma unroll
                for (int c = 0; c < 4; c++) s[mi][ni][c] = 0.f;

#pragma unroll
        for (int ks = 0; ks < 8; ks++) {
            const int kc = tid4 + 8 * ks;
            uint32_t a[2][4], bf[8][2];
#pragma unroll
            for (int mi = 0; mi < 2; mi++) {
                const int r = w * 32 + 16 * mi + g;
                a[mi][0] = Qs[r * AT_STRIDE + kc];
                a[mi][1] = Qs[(r + 8) * AT_STRIDE + kc];
                a[mi][2] = Qs[r * AT_STRIDE + kc + 4];
                a[mi][3] = Qs[(r + 8) * AT_STRIDE + kc + 4];
            }
#pragma unroll
            for (int ni = 0; ni < 8; ni++) {
                const int n = 8 * ni + g;
                bf[ni][0] = Ks[n * AT_STRIDE + kc];
                bf[ni][1] = Ks[n * AT_STRIDE + kc + 4];
            }
#pragma unroll
            for (int mi = 0; mi < 2; mi++)
#pragma unroll
                for (int ni = 0; ni < 8; ni++)
                    mma_tf32(s[mi][ni], a[mi], bf[ni]);
        }

#pragma unroll
        for (int mi = 0; mi < 2; mi++) {
            float mx0 = -1e30f, mx1 = -1e30f;
#pragma unroll
            for (int ni = 0; ni < 8; ni++) {
#pragma unroll
                for (int c = 0; c < 4; c++) s[mi][ni][c] *= 0.125f;
                mx0 = fmaxf(mx0, fmaxf(s[mi][ni][0], s[mi][ni][1]));
                mx1 = fmaxf(mx1, fmaxf(s[mi][ni][2], s[mi][ni][3]));
            }
            mx0 = fmaxf(mx0, __shfl_xor_sync(0xffffffffu, mx0, 1));
            mx0 = fmaxf(mx0, __shfl_xor_sync(0xffffffffu, mx0, 2));
            mx1 = fmaxf(mx1, __shfl_xor_sync(0xffffffffu, mx1, 1));
            mx1 = fmaxf(mx1, __shfl_xor_sync(0xffffffffu, mx1, 2));
            const float mn0 = fmaxf(m_[mi][0], mx0);
            const float mn1 = fmaxf(m_[mi][1], mx1);
            float sum0 = 0.f, sum1 = 0.f;
#pragma unroll
            for (int ni = 0; ni < 8; ni++) {
                s[mi][ni][0] = __expf(s[mi][ni][0] - mn0);
                s[mi][ni][1] = __expf(s[mi][ni][1] - mn0);
                s[mi][ni][2] = __expf(s[mi][ni][2] - mn1);
                s[mi][ni][3] = __expf(s[mi][ni][3] - mn1);
                sum0 += s[mi][ni][0] + s[mi][ni][1];
                sum1 += s[mi][ni][2] + s[mi][ni][3];
            }
            sum0 += __shfl_xor_sync(0xffffffffu, sum0, 1);
            sum0 += __shfl_xor_sync(0xffffffffu, sum0, 2);
            sum1 += __shfl_xor_sync(0xffffffffu, sum1, 1);
            sum1 += __shfl_xor_sync(0xffffffffu, sum1, 2);
            const float al0 = __expf(m_[mi][0] - mn0);
            const float al1 = __expf(m_[mi][1] - mn1);
            m_[mi][0] = mn0; m_[mi][1] = mn1;
            l_[mi][0] = l_[mi][0] * al0 + sum0;
            l_[mi][1] = l_[mi][1] * al1 + sum1;
#pragma unroll
            for (int ni = 0; ni < 8; ni++) {
                o[mi][ni][0] *= al0; o[mi][ni][1] *= al0;
                o[mi][ni][2] *= al1; o[mi][ni][3] *= al1;
            }
            const int r = w * 32 + 16 * mi + g;
#pragma unroll
            for (int ni = 0; ni < 8; ni++) {
                const int col = 2 * tid4 + 8 * ni;
                Ps[r * AT_STRIDE + col]           = f2tf(s[mi][ni][0]);
                Ps[r * AT_STRIDE + col + 1]       = f2tf(s[mi][ni][1]);
                Ps[(r + 8) * AT_STRIDE + col]     = f2tf(s[mi][ni][2]);
                Ps[(r + 8) * AT_STRIDE + col + 1] = f2tf(s[mi][ni][3]);
            }
        }
        __syncwarp();

#pragma unroll
        for (int ks = 0; ks < 8; ks++) {
            const int kc = tid4 + 8 * ks;
            uint32_t a[2][4], bf[8][2];
#pragma unroll
            for (int mi = 0; mi < 2; mi++) {
                const int r = w * 32 + 16 * mi + g;
                a[mi][0] = Ps[r * AT_STRIDE + kc];
                a[mi][1] = Ps[(r + 8) * AT_STRIDE + kc];
                a[mi][2] = Ps[r * AT_STRIDE + kc + 4];
                a[mi][3] = Ps[(r + 8) * AT_STRIDE + kc + 4];
            }
#pragma unroll
            for (int ni = 0; ni < 8; ni++) {
                const int n = 8 * ni + g;
                bf[ni][0] = Vs[kc * AT_STRIDE + n];
                bf[ni][1] = Vs[(kc + 4) * AT_STRIDE + n];
            }
#pragma unroll
            for (int mi = 0; mi < 2; mi++)
#pragma unroll
                for (int ni = 0; ni < 8; ni++)
                    mma_tf32(o[mi][ni], a[mi], bf[ni]);
        }
        __syncwarp();
    }

#pragma unroll
    for (int mi = 0; mi < 2; mi++) {
        const float inv0 = 1.0f / l_[mi][0];
        const float inv1 = 1.0f / l_[mi][1];
        const int r = qb * BQ + w * 32 + 16 * mi + g;
#pragma unroll
        for (int ni = 0; ni < 8; ni++) {
            const int col = h * HD + 2 * tid4 + 8 * ni;
            float2 v0 = make_float2(o[mi][ni][0] * inv0, o[mi][ni][1] * inv0);
            float2 v1 = make_float2(o[mi][ni][2] * inv1, o[mi][ni][3] * inv1);
            *(float2*)(ctx + ((size_t)b * N1V + r) * DIMV + col)     = v0;
            *(float2*)(ctx + ((size_t)b * N1V + r + 8) * DIMV + col) = v1;
        }
    }
}

// ---------------------------------------------------------------------------
// wbo[a] = sum_k W[a][k] * bo[k]   (one warp per output row)
// ---------------------------------------------------------------------------
__global__ __launch_bounds__(256) void gemv_wbo(
    const float* __restrict__ W, const float* __restrict__ bo,
    float* __restrict__ wbo)
{
    const int a = blockIdx.x * 8 + (threadIdx.x >> 5);
    const int lane = threadIdx.x & 31;
    float s = 0.f;
#pragma unroll
    for (int i = 0; i < 4; i++) {
        const int j = lane + 32 * i;
        float4 wv = ((const float4*)(W + (size_t)a * DIMV))[j];
        float4 bv = ((const float4*)bo)[j];
        s += wv.x * bv.x + wv.y * bv.y + wv.z * bv.z + wv.w * bv.w;
    }
#pragma unroll
    for (int off = 16; off; off >>= 1)
        s += __shfl_xor_sync(0xffffffffu, s, off);
    if (lane == 0) wbo[a] = s;
}

// ---------------------------------------------------------------------------
// out[row] = softplus( (dot(ctx[row],u[row]) + dot(g1[row],wbo)) * scale )
// ---------------------------------------------------------------------------
__global__ __launch_bounds__(128) void score_kernel(
    const float* __restrict__ ctx, const float* __restrict__ u,
    const float* __restrict__ g1, const float* __restrict__ wbo,
    const float* __restrict__ scale, float* __restrict__ out)
{
    const int row = blockIdx.x;
    const int t = threadIdx.x;
    const float4 a = ((const float4*)(ctx + (size_t)row * DIMV))[t];
    const float4 b = ((const float4*)(u   + (size_t)row * DIMV))[t];
    const float4 c = ((const float4*)(g1  + (size_t)row * DIMV))[t];
    const float4 d = ((const float4*)wbo)[t];
    float s = a.x * b.x + a.y * b.y + a.z * b.z + a.w * b.w
            + c.x * d.x + c.y * d.y + c.z * d.z + c.w * d.w;
#pragma unroll
    for (int off = 16; off; off >>= 1)
        s += __shfl_xor_sync(0xffffffffu, s, off);
    __shared__ float red[4];
    if ((t & 31) == 0) red[t >> 5] = s;
    __syncthreads();
    if (t == 0) {
        const float tot = red[0] + red[1] + red[2] + red[3];
        const float z = tot * scale[0];
        out[row] = fmaxf(z, 0.f) + log1pf(__expf(-fabsf(z)));
    }
}

// ---------------------------------------------------------------------------
extern "C" void kernel_launch(void* const* d_in, const int* in_sizes, int n_in,
                              void* d_out, int out_size)
{
    const float* g1    = (const float*)d_in[0];
    const float* g2    = (const float*)d_in[1];
    const float* Wq    = (const float*)d_in[2];
    const float* bq    = (const float*)d_in[3];
    const float* Wk    = (const float*)d_in[4];
    const float* bk    = (const float*)d_in[5];
    const float* Wv    = (const float*)d_in[6];
    const float* bv    = (const float*)d_in[7];
    const float* Wo    = (const float*)d_in[8];
    const float* bo    = (const float*)d_in[9];
    const float* Wb    = (const float*)d_in[10];
    const float* scale = (const float*)d_in[11];
    float* out = (float*)d_out;

    float *Qp, *Kp, *Vp, *CTXp, *Up;
    float *g1r, *g2r, *Wqr, *Wkr, *Wvr, *Wor, *Wr, *Mp, *wbop;
    cudaGetSymbolAddress((void**)&Qp,   g_Q);
    cudaGetSymbolAddress((void**)&Kp,   g_K);
    cudaGetSymbolAddress((void**)&Vp,   g_V);
    cudaGetSymbolAddress((void**)&CTXp, g_CTX);
    cudaGetSymbolAddress((void**)&Up,   g_U);
    cudaGetSymbolAddress((void**)&g1r,  g_g1r);
    cudaGetSymbolAddress((void**)&g2r,  g_g2r);
    cudaGetSymbolAddress((void**)&Wqr,  g_Wqr);
    cudaGetSymbolAddress((void**)&Wkr,  g_Wkr);
    cudaGetSymbolAddress((void**)&Wvr,  g_Wvr);
    cudaGetSymbolAddress((void**)&Wor,  g_Wor);
    cudaGetSymbolAddress((void**)&Wr,   g_Wr);
    cudaGetSymbolAddress((void**)&Mp,   g_M);
    cudaGetSymbolAddress((void**)&wbop, g_wbo);

    cudaFuncSetAttribute((const void*)gemm_tc<true,  true,  false>, cudaFuncAttributeMaxDynamicSharedMemorySize, GEMM_SMEM);
    cudaFuncSetAttribute((const void*)gemm_tc<false, false, false>, cudaFuncAttributeMaxDynamicSharedMemorySize, GEMM_SMEM);
    cudaFuncSetAttribute((const void*)gemm_tc<false, false, true >, cudaFuncAttributeMaxDynamicSharedMemorySize, GEMM_SMEM);
    cudaFuncSetAttribute((const void*)attn_tc, cudaFuncAttributeMaxDynamicSharedMemorySize, ATTN_SMEM);

    const int M = BATCH * N1V;                 // 8192
    const int NBIG4 = (M * DIMV) / 4;
    const int NW4   = (DIMV * DIMV) / 4;

    // tf32 pre-round (cp.async GEMMs need rounded operands)
    round_tf32_k<<<(NBIG4 + 255) / 256, 256>>>(g1, g1r, NBIG4);
    round_tf32_k<<<(NBIG4 + 255) / 256, 256>>>(g2, g2r, NBIG4);
    round_tf32_k<<<(NW4 + 255) / 256, 256>>>(Wq, Wqr, NW4);
    round_tf32_k<<<(NW4 + 255) / 256, 256>>>(Wk, Wkr, NW4);
    round_tf32_k<<<(NW4 + 255) / 256, 256>>>(Wv, Wvr, NW4);
    round_tf32_k<<<(NW4 + 255) / 256, 256>>>(Wb, Wr,  NW4);
    round_tf32_k<<<(NW4 + 255) / 256, 256>>>(Wo, Wor, NW4);

    gemv_wbo<<<DIMV / 8, 256>>>(Wb, bo, wbop);

    // M = W @ Wo (512x512x512, NN, rounded output feeds u-gemm)
    gemm_tc<false, false, true ><<<dim3(4, 4), 256, GEMM_SMEM>>>(Wr, Wor, nullptr, Mp, DIMV, DIMV, DIMV);

    dim3 gg(DIMV / 128, M / 128);              // (4, 64)
    gemm_tc<true,  true,  false><<<gg, 256, GEMM_SMEM>>>(g1r, Wqr, bq,      Qp, M, DIMV, DIMV);
    gemm_tc<true,  true,  false><<<gg, 256, GEMM_SMEM>>>(g2r, Wkr, bk,      Kp, M, DIMV, DIMV);
    gemm_tc<true,  true,  false><<<gg, 256, GEMM_SMEM>>>(g2r, Wvr, bv,      Vp, M, DIMV, DIMV);
    gemm_tc<false, false, false><<<gg, 256, GEMM_SMEM>>>(g1r, Mp,  nullptr, Up, M, DIMV, DIMV);

    attn_tc<<<dim3(N1V / BQ, BATCH * NHEAD), 128, ATTN_SMEM>>>(Qp, Kp, Vp, CTXp);

    score_kernel<<<M, 128>>>(CTXp, Up, g1, wbop, scale, out);
}